// round 5
// baseline (speedup 1.0000x reference)
#include <cuda_runtime.h>
#include <cuda_fp16.h>
#include <cstdint>

// ---------------- problem constants ----------------
#define TOKENS   8192
#define NDIM     4096
#define KDIM     4096
#define NGROUPS  32

// ---------------- GEMM tiling ----------------
#define BM 128
#define BN 256
#define BK 64
#define STAGES 3
#define KITERS (KDIM / BK)                  // 64
#define A_STAGE_BYTES (BM * BK * 2)         // 16384
#define B_STAGE_BYTES (BN * BK * 2)         // 32768
#define STAGE_BYTES   (A_STAGE_BYTES + B_STAGE_BYTES)  // 49152
#define SMEM_TOTAL    (STAGES * STAGE_BYTES)           // 147456

// ---------------- scratch (device globals; no allocation) ----------------
__device__ uint16_t g_xh[(size_t)TOKENS * KDIM];   // 64 MB fp16
__device__ uint16_t g_wh[(size_t)NDIM * KDIM];     // 32 MB fp16

// ---------------- PTX helpers (baseline ISA only) ----------------
__device__ __forceinline__ uint32_t smem_to_u32(const void* p) {
    uint32_t a;
    asm("{ .reg .u64 t; cvta.to.shared.u64 t, %1; cvt.u32.u64 %0, t; }" : "=r"(a) : "l"(p));
    return a;
}

#define CP_ASYNC16(dst, src) \
    asm volatile("cp.async.cg.shared.global [%0], [%1], 16;" :: "r"(dst), "l"(src) : "memory")
#define CP_COMMIT() asm volatile("cp.async.commit_group;" ::: "memory")
#define CP_WAIT(n)  asm volatile("cp.async.wait_group %0;" :: "n"(n) : "memory")

#define LDSM4(r0, r1, r2, r3, addr) \
    asm volatile("ldmatrix.sync.aligned.m8n8.x4.shared.b16 {%0,%1,%2,%3}, [%4];" \
                 : "=r"(r0), "=r"(r1), "=r"(r2), "=r"(r3) : "r"(addr))

#define MMA16816(c, a, b0, b1) \
    asm volatile("mma.sync.aligned.m16n8k16.row.col.f32.f16.f16.f32 " \
                 "{%0,%1,%2,%3}, {%4,%5,%6,%7}, {%8,%9}, {%0,%1,%2,%3};" \
                 : "+f"((c)[0]), "+f"((c)[1]), "+f"((c)[2]), "+f"((c)[3]) \
                 : "r"((a)[0]), "r"((a)[1]), "r"((a)[2]), "r"((a)[3]), "r"(b0), "r"(b1))

// ---------------- prepass: x fp32 -> fp16 ----------------
__global__ void __launch_bounds__(256) conv_x_kernel(const float* __restrict__ x,
                                                     uint16_t* __restrict__ xh) {
    size_t i = ((size_t)blockIdx.x * 256 + threadIdx.x) * 8;
    float4 v0 = *reinterpret_cast<const float4*>(x + i);
    float4 v1 = *reinterpret_cast<const float4*>(x + i + 4);
    float vv[8] = {v0.x, v0.y, v0.z, v0.w, v1.x, v1.y, v1.z, v1.w};
    uint16_t h[8];
#pragma unroll
    for (int j = 0; j < 8; j++) h[j] = __half_as_ushort(__float2half_rn(vv[j]));
    *reinterpret_cast<uint4*>(xh + i) = *reinterpret_cast<uint4*>(h);
}

// ---------------- prepass: dequant w -> fp16 ----------------
__global__ void __launch_bounds__(256) conv_w_kernel(const int* __restrict__ q,
                                                     const float* __restrict__ s,
                                                     const float* __restrict__ z,
                                                     uint16_t* __restrict__ wh) {
    size_t i = ((size_t)blockIdx.x * 256 + threadIdx.x) * 8;
    int n = (int)(i >> 12);
    int k = (int)(i & 4095);
    int g = k >> 7;
    float sc = s[n * NGROUPS + g];
    float zz = z[n * NGROUPS + g];
    int4 q0 = *reinterpret_cast<const int4*>(q + i);
    int4 q1 = *reinterpret_cast<const int4*>(q + i + 4);
    int qq[8] = {q0.x, q0.y, q0.z, q0.w, q1.x, q1.y, q1.z, q1.w};
    uint16_t h[8];
#pragma unroll
    for (int j = 0; j < 8; j++)
        h[j] = __half_as_ushort(__float2half_rn((float)qq[j] * sc + zz));
    *reinterpret_cast<uint4*>(wh + i) = *reinterpret_cast<uint4*>(h);
}

// ---------------- GEMM: 256 threads = 8 warps (2m x 4n), warp tile 64x64 --
// Crossbar-traffic-minimized: LDSM bytes/MAC = 2(64+64)/(64*64) = 0.0625.
// smem rows 128B (64 fp16), 16B-chunk XOR swizzle chunk^(row&7).
__global__ void __launch_bounds__(256, 1) gemm_kernel(const float* __restrict__ bias,
                                                      float* __restrict__ out) {
    extern __shared__ char smem[];
    uint32_t sbase = smem_to_u32(smem);
    int tid = threadIdx.x, lane = tid & 31, wid = tid >> 5;
    int wm = wid & 1, wn = wid >> 1;                  // 2 x 4 warp grid
    int m0 = blockIdx.y * BM, n0 = blockIdx.x * BN;

    // ---- loader bases ----
    // A: 128 rows x 8 chunks = 1024 chunks; 4 per thread, row step 32.
    // B: 256 rows x 8 chunks = 2048 chunks; 8 per thread, row step 32.
    int r0 = tid >> 3, c0 = tid & 7;
    uint32_t dstA0 = r0 * 128 + ((c0 ^ (r0 & 7)) << 4);
    const uint16_t* srcA0 = g_xh + (size_t)(m0 + r0) * KDIM + c0 * 8;
    const uint16_t* srcB0 = g_wh + (size_t)(n0 + r0) * KDIM + c0 * 8;

    // ---- ldmatrix per-thread row bases (layout verified R2-R4) ----
    int mBase = wm * 64 + (lane & 15);
    int aHi   = (lane >> 4) & 1;
    int nBase = wn * 64 + (lane & 7) + ((lane & 16) ? 8 : 0);
    int bHi   = (lane >> 3) & 1;

    float acc[4][8][4];
#pragma unroll
    for (int mi = 0; mi < 4; mi++)
#pragma unroll
        for (int ni = 0; ni < 8; ni++)
#pragma unroll
            for (int e = 0; e < 4; e++) acc[mi][ni][e] = 0.f;

    // ---- prologue: fill STAGES-1 stages ----
#pragma unroll
    for (int st = 0; st < STAGES - 1; st++) {
        uint32_t sS = sbase + st * STAGE_BYTES;
        int kt = st * BK;
#pragma unroll
        for (int i = 0; i < 4; i++)
            CP_ASYNC16(sS + dstA0 + i * 4096, srcA0 + kt + (size_t)i * 32 * KDIM);
#pragma unroll
        for (int i = 0; i < 8; i++)
            CP_ASYNC16(sS + A_STAGE_BYTES + dstA0 + i * 4096, srcB0 + kt + (size_t)i * 32 * KDIM);
        CP_COMMIT();
    }

    // ---- mainloop ----
    for (int it = 0; it < KITERS; it++) {
        CP_WAIT(STAGES - 2);
        __syncthreads();

        int pf = it + STAGES - 1;
        if (pf < KITERS) {
            uint32_t sS = sbase + (pf % STAGES) * STAGE_BYTES;
            int kt = pf * BK;
#pragma unroll
            for (int i = 0; i < 4; i++)
                CP_ASYNC16(sS + dstA0 + i * 4096, srcA0 + kt + (size_t)i * 32 * KDIM);
#pragma unroll
            for (int i = 0; i < 8; i++)
                CP_ASYNC16(sS + A_STAGE_BYTES + dstA0 + i * 4096, srcB0 + kt + (size_t)i * 32 * KDIM);
        }
        CP_COMMIT();

        uint32_t sA = sbase + (it % STAGES) * STAGE_BYTES;
        uint32_t sB = sA + A_STAGE_BYTES;
#pragma unroll
        for (int kk = 0; kk < BK / 16; kk++) {
            // load 4 B tiles (16 n-rows each) -> 8 n8k16 fragments
            uint32_t b[4][4];
#pragma unroll
            for (int p = 0; p < 4; p++) {
                int row = nBase + p * 16;
                uint32_t bd = sB + row * 128 + ((((kk << 1) | bHi) ^ (row & 7)) << 4);
                LDSM4(b[p][0], b[p][1], b[p][2], b[p][3], bd);
            }
            // per A tile: load then use immediately (small live set)
#pragma unroll
            for (int mi = 0; mi < 4; mi++) {
                uint32_t a[4];
                int row = mBase + mi * 16;
                uint32_t ad = sA + row * 128 + ((((kk << 1) | aHi) ^ (row & 7)) << 4);
                LDSM4(a[0], a[1], a[2], a[3], ad);
#pragma unroll
                for (int ni = 0; ni < 8; ni++) {
                    uint32_t b0 = b[ni >> 1][(ni & 1) * 2 + 0];
                    uint32_t b1 = b[ni >> 1][(ni & 1) * 2 + 1];
                    MMA16816(acc[mi][ni], a, b0, b1);
                }
            }
        }
    }

    // ---- epilogue: direct gmem stores + bias ----
    int mB = m0 + wm * 64 + (lane >> 2);
    int nB = n0 + wn * 64 + (lane & 3) * 2;
#pragma unroll
    for (int mi = 0; mi < 4; mi++) {
#pragma unroll
        for (int ni = 0; ni < 8; ni++) {
            int m = mB + mi * 16;
            int n = nB + ni * 8;
            float b0 = __ldg(bias + n), b1 = __ldg(bias + n + 1);
            float2 v0 = {acc[mi][ni][0] + b0, acc[mi][ni][1] + b1};
            float2 v1 = {acc[mi][ni][2] + b0, acc[mi][ni][3] + b1};
            *reinterpret_cast<float2*>(out + (size_t)m * NDIM + n) = v0;
            *reinterpret_cast<float2*>(out + (size_t)(m + 8) * NDIM + n) = v1;
        }
    }
}

// ---------------- host ----------------
extern "C" void kernel_launch(void* const* d_in, const int* in_sizes, int n_in,
                              void* d_out, int out_size) {
    (void)in_sizes; (void)n_in; (void)out_size;
    const float* x    = (const float*)d_in[0];
    const int*   q    = (const int*)d_in[1];
    const float* s    = (const float*)d_in[2];
    const float* z    = (const float*)d_in[3];
    const float* bias = (const float*)d_in[4];
    float* out = (float*)d_out;

    void *p_xh, *p_wh;
    cudaGetSymbolAddress(&p_xh, g_xh);
    cudaGetSymbolAddress(&p_wh, g_wh);
    uint16_t* xh = (uint16_t*)p_xh;
    uint16_t* wh = (uint16_t*)p_wh;

    conv_x_kernel<<<(int)(((size_t)TOKENS * KDIM) / (256 * 8)), 256>>>(x, xh);
    conv_w_kernel<<<(int)(((size_t)NDIM * KDIM) / (256 * 8)), 256>>>(q, s, z, wh);

    static bool attr_set = false;
    if (!attr_set) {
        cudaFuncSetAttribute(gemm_kernel, cudaFuncAttributeMaxDynamicSharedMemorySize, SMEM_TOTAL);
        attr_set = true;
    }
    dim3 grid(NDIM / BN, TOKENS / BM);   // (16, 64), n fastest for B reuse in L2
    gemm_kernel<<<grid, 256, SMEM_TOTAL>>>(bias, out);
}

// round 6
// speedup vs baseline: 1.2106x; 1.2106x over previous
#include <cuda_runtime.h>
#include <cuda_fp16.h>
#include <cstdint>

// ---------------- problem constants ----------------
#define TOKENS   8192
#define NDIM     4096
#define KDIM     4096
#define NGROUPS  32

// ---------------- GEMM tiling ----------------
#define BM 128
#define BN 128
#define BK 64
#define STAGES 3
#define KITERS (KDIM / BK)                  // 64
#define A_STAGE_BYTES (BM * BK * 2)         // 16384
#define B_STAGE_BYTES (BN * BK * 2)         // 16384
#define STAGE_BYTES   (A_STAGE_BYTES + B_STAGE_BYTES)  // 32768
#define SMEM_TOTAL    (STAGES * STAGE_BYTES)           // 98304 -> 2 CTAs/SM

// ---------------- scratch (device globals; no allocation) ----------------
__device__ uint16_t g_xh[(size_t)TOKENS * KDIM];   // 64 MB fp16
__device__ uint16_t g_wh[(size_t)NDIM * KDIM];     // 32 MB fp16

// ---------------- PTX helpers (baseline ISA only) ----------------
__device__ __forceinline__ uint32_t smem_to_u32(const void* p) {
    uint32_t a;
    asm("{ .reg .u64 t; cvta.to.shared.u64 t, %1; cvt.u32.u64 %0, t; }" : "=r"(a) : "l"(p));
    return a;
}

#define CP_ASYNC16(dst, src) \
    asm volatile("cp.async.cg.shared.global [%0], [%1], 16;" :: "r"(dst), "l"(src) : "memory")
#define CP_COMMIT() asm volatile("cp.async.commit_group;" ::: "memory")
#define CP_WAIT(n)  asm volatile("cp.async.wait_group %0;" :: "n"(n) : "memory")

#define LDSM4(r0, r1, r2, r3, addr) \
    asm volatile("ldmatrix.sync.aligned.m8n8.x4.shared.b16 {%0,%1,%2,%3}, [%4];" \
                 : "=r"(r0), "=r"(r1), "=r"(r2), "=r"(r3) : "r"(addr))

#define MMA16816(c, a, b0, b1) \
    asm volatile("mma.sync.aligned.m16n8k16.row.col.f32.f16.f16.f32 " \
                 "{%0,%1,%2,%3}, {%4,%5,%6,%7}, {%8,%9}, {%0,%1,%2,%3};" \
                 : "+f"((c)[0]), "+f"((c)[1]), "+f"((c)[2]), "+f"((c)[3]) \
                 : "r"((a)[0]), "r"((a)[1]), "r"((a)[2]), "r"((a)[3]), "r"(b0), "r"(b1))

// ---------------- prepass: x fp32 -> fp16 ----------------
__global__ void __launch_bounds__(256) conv_x_kernel(const float* __restrict__ x,
                                                     uint16_t* __restrict__ xh) {
    size_t i = ((size_t)blockIdx.x * 256 + threadIdx.x) * 8;
    float4 v0 = *reinterpret_cast<const float4*>(x + i);
    float4 v1 = *reinterpret_cast<const float4*>(x + i + 4);
    float vv[8] = {v0.x, v0.y, v0.z, v0.w, v1.x, v1.y, v1.z, v1.w};
    uint16_t h[8];
#pragma unroll
    for (int j = 0; j < 8; j++) h[j] = __half_as_ushort(__float2half_rn(vv[j]));
    *reinterpret_cast<uint4*>(xh + i) = *reinterpret_cast<uint4*>(h);
}

// ---------------- prepass: dequant w -> fp16 ----------------
__global__ void __launch_bounds__(256) conv_w_kernel(const int* __restrict__ q,
                                                     const float* __restrict__ s,
                                                     const float* __restrict__ z,
                                                     uint16_t* __restrict__ wh) {
    size_t i = ((size_t)blockIdx.x * 256 + threadIdx.x) * 8;
    int n = (int)(i >> 12);
    int k = (int)(i & 4095);
    int g = k >> 7;
    float sc = s[n * NGROUPS + g];
    float zz = z[n * NGROUPS + g];
    int4 q0 = *reinterpret_cast<const int4*>(q + i);
    int4 q1 = *reinterpret_cast<const int4*>(q + i + 4);
    int qq[8] = {q0.x, q0.y, q0.z, q0.w, q1.x, q1.y, q1.z, q1.w};
    uint16_t h[8];
#pragma unroll
    for (int j = 0; j < 8; j++)
        h[j] = __half_as_ushort(__float2half_rn((float)qq[j] * sc + zz));
    *reinterpret_cast<uint4*>(wh + i) = *reinterpret_cast<uint4*>(h);
}

// ---------------- GEMM: 128 threads = 4 warps (2m x 2n), warp tile 64x64 --
// 2 CTAs/SM for latency cover; crossbar bytes/MAC = 0.0915 (vs 0.122 @64x32).
// smem rows 128B (64 fp16), 16B-chunk XOR swizzle chunk^(row&7).
__global__ void __launch_bounds__(128, 2) gemm_kernel(const float* __restrict__ bias,
                                                      float* __restrict__ out) {
    extern __shared__ char smem[];
    uint32_t sbase = smem_to_u32(smem);
    int tid = threadIdx.x, lane = tid & 31, wid = tid >> 5;
    int wm = wid & 1, wn = wid >> 1;                  // 2 x 2 warp grid
    int m0 = blockIdx.y * BM, n0 = blockIdx.x * BN;

    // ---- loader bases: 8 A-chunks + 8 B-chunks (16B each) per thread ----
    // 128 threads cover rows r0 + 16*i (i=0..7); (r&7) invariant across i.
    int r0 = tid >> 3, c0 = tid & 7;
    uint32_t dstA0 = r0 * 128 + ((c0 ^ (r0 & 7)) << 4);
    const uint16_t* srcA0 = g_xh + (size_t)(m0 + r0) * KDIM + c0 * 8;
    const uint16_t* srcB0 = g_wh + (size_t)(n0 + r0) * KDIM + c0 * 8;

    // ---- ldmatrix per-thread row bases (layout verified R2-R5) ----
    int mBase = wm * 64 + (lane & 15);
    int aHi   = (lane >> 4) & 1;
    int nBase = wn * 64 + (lane & 7) + ((lane & 16) ? 8 : 0);
    int bHi   = (lane >> 3) & 1;

    float acc[4][8][4];
#pragma unroll
    for (int mi = 0; mi < 4; mi++)
#pragma unroll
        for (int ni = 0; ni < 8; ni++)
#pragma unroll
            for (int e = 0; e < 4; e++) acc[mi][ni][e] = 0.f;

    // ---- prologue: fill STAGES-1 stages ----
#pragma unroll
    for (int st = 0; st < STAGES - 1; st++) {
        uint32_t sS = sbase + st * STAGE_BYTES;
        int kt = st * BK;
#pragma unroll
        for (int i = 0; i < 8; i++) {
            CP_ASYNC16(sS + dstA0 + i * 2048, srcA0 + kt + (size_t)i * 16 * KDIM);
            CP_ASYNC16(sS + A_STAGE_BYTES + dstA0 + i * 2048, srcB0 + kt + (size_t)i * 16 * KDIM);
        }
        CP_COMMIT();
    }

    // ---- mainloop ----
    for (int it = 0; it < KITERS; it++) {
        CP_WAIT(STAGES - 2);
        __syncthreads();

        int pf = it + STAGES - 1;
        if (pf < KITERS) {
            uint32_t sS = sbase + (pf % STAGES) * STAGE_BYTES;
            int kt = pf * BK;
#pragma unroll
            for (int i = 0; i < 8; i++) {
                CP_ASYNC16(sS + dstA0 + i * 2048, srcA0 + kt + (size_t)i * 16 * KDIM);
                CP_ASYNC16(sS + A_STAGE_BYTES + dstA0 + i * 2048, srcB0 + kt + (size_t)i * 16 * KDIM);
            }
        }
        CP_COMMIT();

        uint32_t sA = sbase + (it % STAGES) * STAGE_BYTES;
        uint32_t sB = sA + A_STAGE_BYTES;
#pragma unroll
        for (int kk = 0; kk < BK / 16; kk++) {
            // 4 B tiles (16 n-rows each) -> 8 n8k16 fragments
            uint32_t b[4][4];
#pragma unroll
            for (int p = 0; p < 4; p++) {
                int row = nBase + p * 16;
                uint32_t bd = sB + row * 128 + ((((kk << 1) | bHi) ^ (row & 7)) << 4);
                LDSM4(b[p][0], b[p][1], b[p][2], b[p][3], bd);
            }
            // per A tile: load then use immediately (small live set)
#pragma unroll
            for (int mi = 0; mi < 4; mi++) {
                uint32_t a[4];
                int row = mBase + mi * 16;
                uint32_t ad = sA + row * 128 + ((((kk << 1) | aHi) ^ (row & 7)) << 4);
                LDSM4(a[0], a[1], a[2], a[3], ad);
#pragma unroll
                for (int ni = 0; ni < 8; ni++) {
                    uint32_t b0 = b[ni >> 1][(ni & 1) * 2 + 0];
                    uint32_t b1 = b[ni >> 1][(ni & 1) * 2 + 1];
                    MMA16816(acc[mi][ni], a, b0, b1);
                }
            }
        }
    }

    // ---- epilogue: direct gmem stores + bias ----
    int mB = m0 + wm * 64 + (lane >> 2);
    int nB = n0 + wn * 64 + (lane & 3) * 2;
#pragma unroll
    for (int mi = 0; mi < 4; mi++) {
#pragma unroll
        for (int ni = 0; ni < 8; ni++) {
            int m = mB + mi * 16;
            int n = nB + ni * 8;
            float b0 = __ldg(bias + n), b1 = __ldg(bias + n + 1);
            float2 v0 = {acc[mi][ni][0] + b0, acc[mi][ni][1] + b1};
            float2 v1 = {acc[mi][ni][2] + b0, acc[mi][ni][3] + b1};
            *reinterpret_cast<float2*>(out + (size_t)m * NDIM + n) = v0;
            *reinterpret_cast<float2*>(out + (size_t)(m + 8) * NDIM + n) = v1;
        }
    }
}

// ---------------- host ----------------
extern "C" void kernel_launch(void* const* d_in, const int* in_sizes, int n_in,
                              void* d_out, int out_size) {
    (void)in_sizes; (void)n_in; (void)out_size;
    const float* x    = (const float*)d_in[0];
    const int*   q    = (const int*)d_in[1];
    const float* s    = (const float*)d_in[2];
    const float* z    = (const float*)d_in[3];
    const float* bias = (const float*)d_in[4];
    float* out = (float*)d_out;

    void *p_xh, *p_wh;
    cudaGetSymbolAddress(&p_xh, g_xh);
    cudaGetSymbolAddress(&p_wh, g_wh);
    uint16_t* xh = (uint16_t*)p_xh;
    uint16_t* wh = (uint16_t*)p_wh;

    conv_x_kernel<<<(int)(((size_t)TOKENS * KDIM) / (256 * 8)), 256>>>(x, xh);
    conv_w_kernel<<<(int)(((size_t)NDIM * KDIM) / (256 * 8)), 256>>>(q, s, z, wh);

    static bool attr_set = false;
    if (!attr_set) {
        cudaFuncSetAttribute(gemm_kernel, cudaFuncAttributeMaxDynamicSharedMemorySize, SMEM_TOTAL);
        attr_set = true;
    }
    dim3 grid(NDIM / BN, TOKENS / BM);   // (32, 64), n fastest for B reuse in L2
    gemm_kernel<<<grid, 128, SMEM_TOTAL>>>(bias, out);
}

// round 7
// speedup vs baseline: 1.2278x; 1.0142x over previous
#include <cuda_runtime.h>
#include <cuda_fp16.h>
#include <cstdint>

// ---------------- problem constants ----------------
#define TOKENS   8192
#define NDIM     4096
#define KDIM     4096
#define NGROUPS  32

// ---------------- GEMM tiling ----------------
#define BM 128
#define BN 128
#define BK 64
#define STAGES 3
#define KITERS (KDIM / BK)                  // 64
#define A_STAGE_BYTES (BM * BK * 2)         // 16384
#define B_STAGE_BYTES (BN * BK * 2)         // 16384
#define STAGE_BYTES   (A_STAGE_BYTES + B_STAGE_BYTES)  // 32768
#define SMEM_TOTAL    (STAGES * STAGE_BYTES)           // 98304 -> 2 CTAs/SM

// ---------------- scratch (device globals; no allocation) ----------------
__device__ uint16_t g_xh[(size_t)TOKENS * KDIM];   // 64 MB fp16
__device__ uint16_t g_wh[(size_t)NDIM * KDIM];     // 32 MB fp16

// ---------------- PTX helpers (baseline ISA only) ----------------
__device__ __forceinline__ uint32_t smem_to_u32(const void* p) {
    uint32_t a;
    asm("{ .reg .u64 t; cvta.to.shared.u64 t, %1; cvt.u32.u64 %0, t; }" : "=r"(a) : "l"(p));
    return a;
}

#define CP_ASYNC16(dst, src) \
    asm volatile("cp.async.cg.shared.global [%0], [%1], 16;" :: "r"(dst), "l"(src) : "memory")
#define CP_COMMIT() asm volatile("cp.async.commit_group;" ::: "memory")
#define CP_WAIT(n)  asm volatile("cp.async.wait_group %0;" :: "n"(n) : "memory")

#define LDSM4(r0, r1, r2, r3, addr) \
    asm volatile("ldmatrix.sync.aligned.m8n8.x4.shared.b16 {%0,%1,%2,%3}, [%4];" \
                 : "=r"(r0), "=r"(r1), "=r"(r2), "=r"(r3) : "r"(addr))

#define MMA16816(c, a, b0, b1) \
    asm volatile("mma.sync.aligned.m16n8k16.row.col.f32.f16.f16.f32 " \
                 "{%0,%1,%2,%3}, {%4,%5,%6,%7}, {%8,%9}, {%0,%1,%2,%3};" \
                 : "+f"((c)[0]), "+f"((c)[1]), "+f"((c)[2]), "+f"((c)[3]) \
                 : "r"((a)[0]), "r"((a)[1]), "r"((a)[2]), "r"((a)[3]), "r"(b0), "r"(b1))

// ---------------- prepass: x fp32 -> fp16 ----------------
__global__ void __launch_bounds__(256) conv_x_kernel(const float* __restrict__ x,
                                                     uint16_t* __restrict__ xh) {
    size_t i = ((size_t)blockIdx.x * 256 + threadIdx.x) * 8;
    float4 v0 = *reinterpret_cast<const float4*>(x + i);
    float4 v1 = *reinterpret_cast<const float4*>(x + i + 4);
    float vv[8] = {v0.x, v0.y, v0.z, v0.w, v1.x, v1.y, v1.z, v1.w};
    uint16_t h[8];
#pragma unroll
    for (int j = 0; j < 8; j++) h[j] = __half_as_ushort(__float2half_rn(vv[j]));
    *reinterpret_cast<uint4*>(xh + i) = *reinterpret_cast<uint4*>(h);
}

// ---------------- prepass: dequant w -> fp16 ----------------
__global__ void __launch_bounds__(256) conv_w_kernel(const int* __restrict__ q,
                                                     const float* __restrict__ s,
                                                     const float* __restrict__ z,
                                                     uint16_t* __restrict__ wh) {
    size_t i = ((size_t)blockIdx.x * 256 + threadIdx.x) * 8;
    int n = (int)(i >> 12);
    int k = (int)(i & 4095);
    int g = k >> 7;
    float sc = s[n * NGROUPS + g];
    float zz = z[n * NGROUPS + g];
    int4 q0 = *reinterpret_cast<const int4*>(q + i);
    int4 q1 = *reinterpret_cast<const int4*>(q + i + 4);
    int qq[8] = {q0.x, q0.y, q0.z, q0.w, q1.x, q1.y, q1.z, q1.w};
    uint16_t h[8];
#pragma unroll
    for (int j = 0; j < 8; j++)
        h[j] = __half_as_ushort(__float2half_rn((float)qq[j] * sc + zz));
    *reinterpret_cast<uint4*>(wh + i) = *reinterpret_cast<uint4*>(h);
}

// ---------------- GEMM: 128 threads = 4 warps (2m x 2n), warp tile 64x64 --
// 2 CTAs/SM; fragment double-buffering hides LDSM latency behind MMA blocks.
// smem rows 128B (64 fp16), 16B-chunk XOR swizzle chunk^(row&7).
__global__ void __launch_bounds__(128, 2) gemm_kernel(const float* __restrict__ bias,
                                                      float* __restrict__ out) {
    extern __shared__ char smem[];
    uint32_t sbase = smem_to_u32(smem);
    int tid = threadIdx.x, lane = tid & 31, wid = tid >> 5;
    int wm = wid & 1, wn = wid >> 1;                  // 2 x 2 warp grid
    int m0 = blockIdx.y * BM, n0 = blockIdx.x * BN;

    // ---- loader bases: 8 A-chunks + 8 B-chunks (16B each) per thread ----
    int r0 = tid >> 3, c0 = tid & 7;
    uint32_t dstA0 = r0 * 128 + ((c0 ^ (r0 & 7)) << 4);
    const uint16_t* srcA0 = g_xh + (size_t)(m0 + r0) * KDIM + c0 * 8;
    const uint16_t* srcB0 = g_wh + (size_t)(n0 + r0) * KDIM + c0 * 8;

    // ---- ldmatrix per-thread row bases (layout verified R2-R6) ----
    int mBase = wm * 64 + (lane & 15);
    int aHi   = (lane >> 4) & 1;
    int nBase = wn * 64 + (lane & 7) + ((lane & 16) ? 8 : 0);
    int bHi   = (lane >> 3) & 1;

    // precompute per-mi/p swizzled offsets relative to stage base (kk=0)
    uint32_t aOff[4], bOff[4];
#pragma unroll
    for (int mi = 0; mi < 4; mi++) {
        int row = mBase + mi * 16;
        aOff[mi] = row * 128 + (((aHi) ^ (row & 7)) << 4);
    }
#pragma unroll
    for (int p = 0; p < 4; p++) {
        int row = nBase + p * 16;
        bOff[p] = row * 128 + (((bHi) ^ (row & 7)) << 4);
    }
    // kk advance: chunk index (kk<<1)|hi; xor with row&7 -> offset delta is
    // ((c ^ s) << 4) where c = kk*2 + hi. Since base already folds hi and row,
    // recompute per kk as: off ^ precomputed? Simpler: full recompute helper.
#define A_ADDR(sA, mi, kk) ((sA) + ((mBase + (mi) * 16) * 128) + \
    (((((kk) << 1) | aHi) ^ ((mBase + (mi) * 16) & 7)) << 4))
#define B_ADDR(sB, p, kk) ((sB) + ((nBase + (p) * 16) * 128) + \
    (((((kk) << 1) | bHi) ^ ((nBase + (p) * 16) & 7)) << 4))

    float acc[4][8][4];
#pragma unroll
    for (int mi = 0; mi < 4; mi++)
#pragma unroll
        for (int ni = 0; ni < 8; ni++)
#pragma unroll
            for (int e = 0; e < 4; e++) acc[mi][ni][e] = 0.f;

    // ---- prologue: fill STAGES-1 stages ----
#pragma unroll
    for (int st = 0; st < STAGES - 1; st++) {
        uint32_t sS = sbase + st * STAGE_BYTES;
        int kt = st * BK;
#pragma unroll
        for (int i = 0; i < 8; i++) {
            CP_ASYNC16(sS + dstA0 + i * 2048, srcA0 + kt + (size_t)i * 16 * KDIM);
            CP_ASYNC16(sS + A_STAGE_BYTES + dstA0 + i * 2048, srcB0 + kt + (size_t)i * 16 * KDIM);
        }
        CP_COMMIT();
    }

    // ---- mainloop ----
    for (int it = 0; it < KITERS; it++) {
        CP_WAIT(STAGES - 2);
        __syncthreads();

        uint32_t sA = sbase + (it % STAGES) * STAGE_BYTES;
        uint32_t sB = sA + A_STAGE_BYTES;

        // issue first fragment loads (kk=0 B, idx=0 A) BEFORE the cp.async
        // burst so the ~128 cyc of cp.async issue hides their latency
        uint32_t b[2][4][4];
        uint32_t a[2][4];
#pragma unroll
        for (int p = 0; p < 4; p++)
            LDSM4(b[0][p][0], b[0][p][1], b[0][p][2], b[0][p][3], B_ADDR(sB, p, 0));
        LDSM4(a[0][0], a[0][1], a[0][2], a[0][3], A_ADDR(sA, 0, 0));

        int pf = it + STAGES - 1;
        if (pf < KITERS) {
            uint32_t sS = sbase + (pf % STAGES) * STAGE_BYTES;
            int kt = pf * BK;
#pragma unroll
            for (int i = 0; i < 8; i++) {
                CP_ASYNC16(sS + dstA0 + i * 2048, srcA0 + kt + (size_t)i * 16 * KDIM);
                CP_ASYNC16(sS + A_STAGE_BYTES + dstA0 + i * 2048, srcB0 + kt + (size_t)i * 16 * KDIM);
            }
        }
        CP_COMMIT();

        // pipelined MMA: idx = kk*4 + mi, fragments double-buffered
#pragma unroll
        for (int kk = 0; kk < 4; kk++) {
            int cb = kk & 1;
            // prefetch next kk's B fragments at the head of this kk block
            if (kk < 3) {
#pragma unroll
                for (int p = 0; p < 4; p++)
                    LDSM4(b[cb ^ 1][p][0], b[cb ^ 1][p][1], b[cb ^ 1][p][2], b[cb ^ 1][p][3],
                          B_ADDR(sB, p, kk + 1));
            }
#pragma unroll
            for (int mi = 0; mi < 4; mi++) {
                int idx = kk * 4 + mi;
                int ca = idx & 1;
                // prefetch next A fragment
                if (idx < 15) {
                    int nidx = idx + 1;
                    int nkk = nidx >> 2, nmi = nidx & 3;
                    LDSM4(a[ca ^ 1][0], a[ca ^ 1][1], a[ca ^ 1][2], a[ca ^ 1][3],
                          A_ADDR(sA, nmi, nkk));
                }
#pragma unroll
                for (int ni = 0; ni < 8; ni++) {
                    uint32_t b0 = b[cb][ni >> 1][(ni & 1) * 2 + 0];
                    uint32_t b1 = b[cb][ni >> 1][(ni & 1) * 2 + 1];
                    MMA16816(acc[mi][ni], a[ca], b0, b1);
                }
            }
        }
    }

    // ---- epilogue: direct gmem stores + bias ----
    int mB = m0 + wm * 64 + (lane >> 2);
    int nB = n0 + wn * 64 + (lane & 3) * 2;
#pragma unroll
    for (int mi = 0; mi < 4; mi++) {
#pragma unroll
        for (int ni = 0; ni < 8; ni++) {
            int m = mB + mi * 16;
            int n = nB + ni * 8;
            float b0 = __ldg(bias + n), b1 = __ldg(bias + n + 1);
            float2 v0 = {acc[mi][ni][0] + b0, acc[mi][ni][1] + b1};
            float2 v1 = {acc[mi][ni][2] + b0, acc[mi][ni][3] + b1};
            *reinterpret_cast<float2*>(out + (size_t)m * NDIM + n) = v0;
            *reinterpret_cast<float2*>(out + (size_t)(m + 8) * NDIM + n) = v1;
        }
    }
}

// ---------------- host ----------------
extern "C" void kernel_launch(void* const* d_in, const int* in_sizes, int n_in,
                              void* d_out, int out_size) {
    (void)in_sizes; (void)n_in; (void)out_size;
    const float* x    = (const float*)d_in[0];
    const int*   q    = (const int*)d_in[1];
    const float* s    = (const float*)d_in[2];
    const float* z    = (const float*)d_in[3];
    const float* bias = (const float*)d_in[4];
    float* out = (float*)d_out;

    void *p_xh, *p_wh;
    cudaGetSymbolAddress(&p_xh, g_xh);
    cudaGetSymbolAddress(&p_wh, g_wh);
    uint16_t* xh = (uint16_t*)p_xh;
    uint16_t* wh = (uint16_t*)p_wh;

    conv_x_kernel<<<(int)(((size_t)TOKENS * KDIM) / (256 * 8)), 256>>>(x, xh);
    conv_w_kernel<<<(int)(((size_t)NDIM * KDIM) / (256 * 8)), 256>>>(q, s, z, wh);

    static bool attr_set = false;
    if (!attr_set) {
        cudaFuncSetAttribute(gemm_kernel, cudaFuncAttributeMaxDynamicSharedMemorySize, SMEM_TOTAL);
        attr_set = true;
    }
    dim3 grid(NDIM / BN, TOKENS / BM);   // (32, 64), n fastest for B reuse in L2
    gemm_kernel<<<grid, 128, SMEM_TOTAL>>>(bias, out);
}

// round 8
// speedup vs baseline: 1.2330x; 1.0042x over previous
#include <cuda_runtime.h>
#include <cuda_fp16.h>
#include <cstdint>

// ---------------- problem constants ----------------
#define TOKENS   8192
#define NDIM     4096
#define KDIM     4096
#define NGROUPS  32

// ---------------- GEMM tiling ----------------
#define BM 128
#define BN 128
#define BK 64
#define STAGES 3
#define KITERS (KDIM / BK)                  // 64
#define NTILES ((NDIM / BN) * (TOKENS / BM))   // 32 * 64 = 2048
#define NCTAS  296                          // 2 per SM, persistent
#define A_STAGE_BYTES (BM * BK * 2)         // 16384
#define B_STAGE_BYTES (BN * BK * 2)         // 16384
#define STAGE_BYTES   (A_STAGE_BYTES + B_STAGE_BYTES)  // 32768
#define SMEM_TOTAL    (STAGES * STAGE_BYTES)           // 98304 -> 2 CTAs/SM

// ---------------- scratch (device globals; no allocation) ----------------
__device__ uint16_t g_xh[(size_t)TOKENS * KDIM];   // 64 MB fp16
__device__ uint16_t g_wh[(size_t)NDIM * KDIM];     // 32 MB fp16

// ---------------- PTX helpers (baseline ISA only) ----------------
__device__ __forceinline__ uint32_t smem_to_u32(const void* p) {
    uint32_t a;
    asm("{ .reg .u64 t; cvta.to.shared.u64 t, %1; cvt.u32.u64 %0, t; }" : "=r"(a) : "l"(p));
    return a;
}

#define CP_ASYNC16(dst, src) \
    asm volatile("cp.async.cg.shared.global [%0], [%1], 16;" :: "r"(dst), "l"(src) : "memory")
#define CP_COMMIT() asm volatile("cp.async.commit_group;" ::: "memory")
#define CP_WAIT(n)  asm volatile("cp.async.wait_group %0;" :: "n"(n) : "memory")

#define LDSM4(r0, r1, r2, r3, addr) \
    asm volatile("ldmatrix.sync.aligned.m8n8.x4.shared.b16 {%0,%1,%2,%3}, [%4];" \
                 : "=r"(r0), "=r"(r1), "=r"(r2), "=r"(r3) : "r"(addr))

#define MMA16816(c, a, b0, b1) \
    asm volatile("mma.sync.aligned.m16n8k16.row.col.f32.f16.f16.f32 " \
                 "{%0,%1,%2,%3}, {%4,%5,%6,%7}, {%8,%9}, {%0,%1,%2,%3};" \
                 : "+f"((c)[0]), "+f"((c)[1]), "+f"((c)[2]), "+f"((c)[3]) \
                 : "r"((a)[0]), "r"((a)[1]), "r"((a)[2]), "r"((a)[3]), "r"(b0), "r"(b1))

// ---------------- fused prepass: x -> fp16, w dequant -> fp16 ------------
#define XBLKS ((int)(((size_t)TOKENS * KDIM) / (256 * 8)))   // 16384
#define WBLKS ((int)(((size_t)NDIM * KDIM) / (256 * 8)))     // 8192

__global__ void __launch_bounds__(256) conv_fused_kernel(
    const float* __restrict__ x, const int* __restrict__ q,
    const float* __restrict__ s, const float* __restrict__ z,
    uint16_t* __restrict__ xh, uint16_t* __restrict__ wh)
{
    int b = blockIdx.x;
    if (b < XBLKS) {
        size_t i = ((size_t)b * 256 + threadIdx.x) * 8;
        float4 v0 = *reinterpret_cast<const float4*>(x + i);
        float4 v1 = *reinterpret_cast<const float4*>(x + i + 4);
        float vv[8] = {v0.x, v0.y, v0.z, v0.w, v1.x, v1.y, v1.z, v1.w};
        uint16_t h[8];
#pragma unroll
        for (int j = 0; j < 8; j++) h[j] = __half_as_ushort(__float2half_rn(vv[j]));
        *reinterpret_cast<uint4*>(xh + i) = *reinterpret_cast<uint4*>(h);
    } else {
        size_t i = ((size_t)(b - XBLKS) * 256 + threadIdx.x) * 8;
        int n = (int)(i >> 12);
        int k = (int)(i & 4095);
        int g = k >> 7;
        float sc = s[n * NGROUPS + g];
        float zz = z[n * NGROUPS + g];
        int4 q0 = *reinterpret_cast<const int4*>(q + i);
        int4 q1 = *reinterpret_cast<const int4*>(q + i + 4);
        int qq[8] = {q0.x, q0.y, q0.z, q0.w, q1.x, q1.y, q1.z, q1.w};
        uint16_t h[8];
#pragma unroll
        for (int j = 0; j < 8; j++)
            h[j] = __half_as_ushort(__float2half_rn((float)qq[j] * sc + zz));
        *reinterpret_cast<uint4*>(wh + i) = *reinterpret_cast<uint4*>(h);
    }
}

// ---------------- persistent GEMM ----------------------------------------
// 296 CTAs (2/SM), each runs 6-7 tiles with a continuous cp.async stage ring
// across tile boundaries: the tail iterations of tile t prefetch tile t+1's
// first k-chunks, so the pipe never drains and the epilogue overlaps loads.
// 128 threads = 4 warps (2m x 2n), warp tile 64x64, fragments double-buffered.
__global__ void __launch_bounds__(128, 2) gemm_kernel(const float* __restrict__ bias,
                                                      float* __restrict__ out) {
    extern __shared__ char smem[];
    uint32_t sbase = smem_to_u32(smem);
    int tid = threadIdx.x, lane = tid & 31, wid = tid >> 5;
    int wm = wid & 1, wn = wid >> 1;                  // 2 x 2 warp grid
    int bid = blockIdx.x;
    int nMine = (NTILES - bid + NCTAS - 1) / NCTAS;   // 6 or 7 tiles
    int totStream = nMine * KITERS;

    // ---- loader thread constants ----
    int r0 = tid >> 3, c0 = tid & 7;
    uint32_t dstA0 = r0 * 128 + ((c0 ^ (r0 & 7)) << 4);
    int srcRowA = r0, srcCol = c0 * 8;                 // + m0/n0 per tile

    // ---- ldmatrix per-thread row bases (layout verified R2-R7) ----
    int mBase = wm * 64 + (lane & 15);
    int aHi   = (lane >> 4) & 1;
    int nBase = wn * 64 + (lane & 7) + ((lane & 16) ? 8 : 0);
    int bHi   = (lane >> 3) & 1;

#define A_ADDR(sA, mi, kk) ((sA) + ((mBase + (mi) * 16) * 128) + \
    (((((kk) << 1) | aHi) ^ ((mBase + (mi) * 16) & 7)) << 4))
#define B_ADDR(sB, p, kk) ((sB) + ((nBase + (p) * 16) * 128) + \
    (((((kk) << 1) | bHi) ^ ((nBase + (p) * 16) & 7)) << 4))

    // prefetch issuer for stream position pf (tile-aware)
#define ISSUE_PF(pf) do {                                                      \
    int pj = (pf) >> 6;                                                        \
    int pk = ((pf) & 63) * BK;                                                 \
    int pt = bid + NCTAS * pj;                                                 \
    int pm0 = (pt >> 5) * BM, pn0 = (pt & 31) * BN;                            \
    uint32_t sS = sbase + ((pf) % STAGES) * STAGE_BYTES;                       \
    const uint16_t* pA = g_xh + (size_t)(pm0 + srcRowA) * KDIM + srcCol + pk;  \
    const uint16_t* pB = g_wh + (size_t)(pn0 + srcRowA) * KDIM + srcCol + pk;  \
    _Pragma("unroll")                                                          \
    for (int i = 0; i < 8; i++) {                                              \
        CP_ASYNC16(sS + dstA0 + i * 2048, pA + (size_t)i * 16 * KDIM);         \
        CP_ASYNC16(sS + A_STAGE_BYTES + dstA0 + i * 2048, pB + (size_t)i * 16 * KDIM); \
    } } while (0)

    // ---- prologue: fill stream positions 0, 1 ----
#pragma unroll
    for (int p = 0; p < STAGES - 1; p++) {
        ISSUE_PF(p);
        CP_COMMIT();
    }

    int pos = 0;
    for (int j = 0; j < nMine; j++) {
        int t = bid + NCTAS * j;
        int m0 = (t >> 5) * BM, n0 = (t & 31) * BN;

        float acc[4][8][4];
#pragma unroll
        for (int mi = 0; mi < 4; mi++)
#pragma unroll
            for (int ni = 0; ni < 8; ni++)
#pragma unroll
                for (int e = 0; e < 4; e++) acc[mi][ni][e] = 0.f;

        for (int it = 0; it < KITERS; it++, pos++) {
            CP_WAIT(STAGES - 2);
            __syncthreads();

            uint32_t sA = sbase + (pos % STAGES) * STAGE_BYTES;
            uint32_t sB = sA + A_STAGE_BYTES;

            // first fragments before the cp.async burst (hide LDSM latency)
            uint32_t b[2][4][4];
            uint32_t a[2][4];
#pragma unroll
            for (int p = 0; p < 4; p++)
                LDSM4(b[0][p][0], b[0][p][1], b[0][p][2], b[0][p][3], B_ADDR(sB, p, 0));
            LDSM4(a[0][0], a[0][1], a[0][2], a[0][3], A_ADDR(sA, 0, 0));

            int pf = pos + STAGES - 1;
            if (pf < totStream) ISSUE_PF(pf);
            CP_COMMIT();

            // pipelined MMA: idx = kk*4 + mi, fragments double-buffered
#pragma unroll
            for (int kk = 0; kk < 4; kk++) {
                int cb = kk & 1;
                if (kk < 3) {
#pragma unroll
                    for (int p = 0; p < 4; p++)
                        LDSM4(b[cb ^ 1][p][0], b[cb ^ 1][p][1], b[cb ^ 1][p][2], b[cb ^ 1][p][3],
                              B_ADDR(sB, p, kk + 1));
                }
#pragma unroll
                for (int mi = 0; mi < 4; mi++) {
                    int idx = kk * 4 + mi;
                    int ca = idx & 1;
                    if (idx < 15) {
                        int nidx = idx + 1;
                        int nkk = nidx >> 2, nmi = nidx & 3;
                        LDSM4(a[ca ^ 1][0], a[ca ^ 1][1], a[ca ^ 1][2], a[ca ^ 1][3],
                              A_ADDR(sA, nmi, nkk));
                    }
#pragma unroll
                    for (int ni = 0; ni < 8; ni++) {
                        uint32_t b0 = b[cb][ni >> 1][(ni & 1) * 2 + 0];
                        uint32_t b1 = b[cb][ni >> 1][(ni & 1) * 2 + 1];
                        MMA16816(acc[mi][ni], a[ca], b0, b1);
                    }
                }
            }
        }

        // ---- epilogue for tile t (overlaps next tile's in-flight loads) ----
        int mB = m0 + wm * 64 + (lane >> 2);
        int nB = n0 + wn * 64 + (lane & 3) * 2;
        float bv[16];
#pragma unroll
        for (int ni = 0; ni < 8; ni++) {
            bv[ni * 2 + 0] = __ldg(bias + nB + ni * 8);
            bv[ni * 2 + 1] = __ldg(bias + nB + ni * 8 + 1);
        }
#pragma unroll
        for (int mi = 0; mi < 4; mi++) {
#pragma unroll
            for (int ni = 0; ni < 8; ni++) {
                int m = mB + mi * 16;
                int n = nB + ni * 8;
                float2 v0 = {acc[mi][ni][0] + bv[ni * 2], acc[mi][ni][1] + bv[ni * 2 + 1]};
                float2 v1 = {acc[mi][ni][2] + bv[ni * 2], acc[mi][ni][3] + bv[ni * 2 + 1]};
                *reinterpret_cast<float2*>(out + (size_t)m * NDIM + n) = v0;
                *reinterpret_cast<float2*>(out + (size_t)(m + 8) * NDIM + n) = v1;
            }
        }
    }
}

// ---------------- host ----------------
extern "C" void kernel_launch(void* const* d_in, const int* in_sizes, int n_in,
                              void* d_out, int out_size) {
    (void)in_sizes; (void)n_in; (void)out_size;
    const float* x    = (const float*)d_in[0];
    const int*   q    = (const int*)d_in[1];
    const float* s    = (const float*)d_in[2];
    const float* z    = (const float*)d_in[3];
    const float* bias = (const float*)d_in[4];
    float* out = (float*)d_out;

    void *p_xh, *p_wh;
    cudaGetSymbolAddress(&p_xh, g_xh);
    cudaGetSymbolAddress(&p_wh, g_wh);

    conv_fused_kernel<<<XBLKS + WBLKS, 256>>>(x, q, s, z,
                                              (uint16_t*)p_xh, (uint16_t*)p_wh);

    cudaFuncSetAttribute(gemm_kernel, cudaFuncAttributeMaxDynamicSharedMemorySize, SMEM_TOTAL);
    gemm_kernel<<<NCTAS, 128, SMEM_TOTAL>>>(bias, out);
}